// round 12
// baseline (speedup 1.0000x reference)
#include <cuda_runtime.h>
#include <cstdint>

// ---------------------------------------------------------------------------
// Problem constants: B=1, T=256, D=512, H=8, DH=64
// proj layout: [t, 5*512]; chunks k1@0, k2@512, q@1024, v1@1536, v2@2048.
// ---------------------------------------------------------------------------
#define T 256
#define D 512
#define H 8
#define DH 64
#define SST 66   // smem row stride (elements: floats or ULLs)

// Packed fp32x2 FMA (sm_100+)
#define FMA2(acc, a, b) asm("fma.rn.f32x2 %0, %1, %2, %0;" : "+l"(acc) : "l"(a), "l"(b))
#define DUP2(dst, f)    asm("mov.b64 %0, {%1, %1};" : "=l"(dst) : "r"(__float_as_uint(f)))
static __device__ __forceinline__ float lo2(unsigned long long v) { return __uint_as_float((unsigned int)v); }
static __device__ __forceinline__ float hi2(unsigned long long v) { return __uint_as_float((unsigned int)(v >> 32)); }

// 16x FFMA2 rank-1 update: acc[4][4] += apair[4] x bdup[4]
#define RANK1_FMA2(ACC, AR, B0, B1, B2, B3)                         \
    do {                                                            \
        unsigned long long _a0 = (AR)[0], _a1 = (AR)[1];            \
        unsigned long long _a2 = (AR)[2], _a3 = (AR)[3];            \
        FMA2(ACC[0][0], _a0, B0); FMA2(ACC[0][1], _a0, B1);         \
        FMA2(ACC[0][2], _a0, B2); FMA2(ACC[0][3], _a0, B3);         \
        FMA2(ACC[1][0], _a1, B0); FMA2(ACC[1][1], _a1, B1);         \
        FMA2(ACC[1][2], _a1, B2); FMA2(ACC[1][3], _a1, B3);         \
        FMA2(ACC[2][0], _a2, B0); FMA2(ACC[2][1], _a2, B1);         \
        FMA2(ACC[2][2], _a2, B2); FMA2(ACC[2][3], _a2, B3);         \
        FMA2(ACC[3][0], _a3, B0); FMA2(ACC[3][1], _a3, B1);         \
        FMA2(ACC[3][2], _a3, B2); FMA2(ACC[3][3], _a3, B3);         \
    } while (0)

// Broadcast mainloop for the generic gemm (unchanged).
#define GEMM64(ACC, Abase, Bbase)                                            \
    do {                                                                     \
        _Pragma("unroll 16")                                                 \
        for (int kk = 0; kk < 64; kk++) {                                    \
            const unsigned long long* arow =                                 \
                reinterpret_cast<const unsigned long long*>(                 \
                    &(Abase)[kk * SST + ty * 8]);                            \
            unsigned long long b0, b1, b2, b3;                               \
            DUP2(b0, (Bbase)[kk * SST + tx * 4 + 0]);                        \
            DUP2(b1, (Bbase)[kk * SST + tx * 4 + 1]);                        \
            DUP2(b2, (Bbase)[kk * SST + tx * 4 + 2]);                        \
            DUP2(b3, (Bbase)[kk * SST + tx * 4 + 3]);                        \
            RANK1_FMA2(ACC, arow, b0, b1, b2, b3);                           \
        }                                                                    \
    } while (0)

// Dup-B mainloop: B-side pre-duplicated ULLs, cols tx+16j, no DUP/half LDS.
#define GEMM64D(ACC, Abase, Bdase)                                           \
    do {                                                                     \
        _Pragma("unroll 16")                                                 \
        for (int kk = 0; kk < 64; kk++) {                                    \
            const unsigned long long* arow =                                 \
                reinterpret_cast<const unsigned long long*>(                 \
                    &(Abase)[kk * SST + ty * 8]);                            \
            const unsigned long long* brow = &(Bdase)[kk * SST + tx];        \
            unsigned long long b0 = brow[0],  b1 = brow[16];                 \
            unsigned long long b2 = brow[32], b3 = brow[48];                 \
            RANK1_FMA2(ACC, arow, b0, b1, b2, b3);                           \
        }                                                                    \
    } while (0)

// Scratch (device globals — allocation-free rule)
__device__ float g_proj[T * 5 * D];
__device__ float g_K1W[H * T * DH * DH];
__device__ float g_Vq1[H * T * DH * DH];
__device__ float g_spart[H * T * T];     // [h][p][q]
__device__ float g_rowinv[H * T];
__device__ float g_z[T * H * DH];        // [q][h*64+e], unscaled

// ---------------------------------------------------------------------------
// Generic batched tiled GEMM (unchanged from round 9).
// ---------------------------------------------------------------------------
__global__ __launch_bounds__(128)
void gemm_kernel(const float* __restrict__ A, const float* __restrict__ Bm,
                 float* __restrict__ C,
                 int lda, int ldb, int ldc,
                 int M, int N, int K, int P,
                 long long aH, long long aP,
                 long long bH, long long bP,
                 long long cH, long long cP,
                 int transB,
                 const float* __restrict__ bias,
                 const float* __restrict__ rowscale, int rsH,
                 int mode, int ksplit)
{
    int bz = blockIdx.z;
    int b  = bz / ksplit;
    int kc = bz % ksplit;
    int h = b / P, p = b % P;
    A  += (long long)h * aH + (long long)p * aP;
    Bm += (long long)h * bH + (long long)p * bP;
    C  += (long long)h * cH + (long long)p * cP;

    int m0 = blockIdx.y * 64;
    int n0 = blockIdx.x * 64;

    int k_begin = 0, k_end = K;
    if (ksplit > 1) { int kchunk = K / ksplit; k_begin = kc * kchunk; k_end = k_begin + kchunk; }

    __shared__ float As[64][SST];
    __shared__ float Bs[64][SST];

    int tid = threadIdx.x;
    int ty = tid >> 4, tx = tid & 15;

    unsigned long long acc2[4][4];
    #pragma unroll
    for (int i = 0; i < 4; i++)
        #pragma unroll
        for (int j = 0; j < 4; j++) acc2[i][j] = 0ULL;

    for (int k0 = k_begin; k0 < k_end; k0 += 64) {
        if (mode == 5) {
            #pragma unroll 8
            for (int i = tid; i < 4096; i += 128) {
                int r = i >> 6, kk = i & 63;
                int kg = k0 + kk, m = m0 + r;
                As[kk][r] = A[(long long)m * lda + kg] * rowscale[(kg >> 6) * T + m];
            }
        } else {
            #pragma unroll 8
            for (int i = tid; i < 4096; i += 128) {
                int r = i >> 6, kk = i & 63;
                As[kk][r] = A[(long long)(m0 + r) * lda + (k0 + kk)];
            }
        }
        if (transB) {
            #pragma unroll 8
            for (int i = tid; i < 4096; i += 128) {
                int n = i >> 6, kk = i & 63;
                Bs[kk][n] = Bm[(long long)(n0 + n) * ldb + (k0 + kk)];
            }
        } else {
            #pragma unroll 8
            for (int i = tid; i < 4096; i += 128) {
                int kk = i >> 6, n = i & 63;
                Bs[kk][n] = Bm[(long long)(k0 + kk) * ldb + (n0 + n)];
            }
        }
        __syncthreads();
        GEMM64(acc2, (&As[0][0]), (&Bs[0][0]));
        __syncthreads();
    }

    int n = n0 + tx * 4;
    float4 bv4 = {0,0,0,0};
    if (bias) { bv4.x = bias[n]; bv4.y = bias[n+1]; bv4.z = bias[n+2]; bv4.w = bias[n+3]; }
    #pragma unroll
    for (int ip = 0; ip < 4; ip++) {
        #pragma unroll
        for (int half = 0; half < 2; half++) {
            int m = m0 + ty * 8 + ip * 2 + half;
            float scale = (rowscale && mode != 5) ? rowscale[h * rsH + m] : 1.0f;
            float4 v;
            v.x = (half ? hi2(acc2[ip][0]) : lo2(acc2[ip][0])) * scale + bv4.x;
            v.y = (half ? hi2(acc2[ip][1]) : lo2(acc2[ip][1])) * scale + bv4.y;
            v.z = (half ? hi2(acc2[ip][2]) : lo2(acc2[ip][2])) * scale + bv4.z;
            v.w = (half ? hi2(acc2[ip][3]) : lo2(acc2[ip][3])) * scale + bv4.w;
            if (ksplit > 1) {
                atomicAdd(&C[(long long)m * ldc + n + 0], v.x);
                atomicAdd(&C[(long long)m * ldc + n + 1], v.y);
                atomicAdd(&C[(long long)m * ldc + n + 2], v.z);
                atomicAdd(&C[(long long)m * ldc + n + 3], v.w);
            } else {
                *reinterpret_cast<float4*>(&C[(long long)m * ldc + n]) = v;
            }
        }
    }
}

// ---------------------------------------------------------------------------
// Fully fused attention inner, dup-B microkernel.
// per (h, p, qtile):
//   Phase1: St[j][q] = sum_i q_h[q,i] * K1W[h][p][j,i]
//   Per t-tile tt <= qt:
//     e[q][t] = (q>=p && t<=q) ? exp(logit/64) : 0
//     A2acc[q][c] += sum_t e[t][q] * v2[t][c]
//   GEMM3: zpart[q][e] = sum_c A2t[c][q] * Vq1[h][p*64+c][e] -> atomics to z
// smem: Bd (dup ULL, 33.8KB, shared by K1W/k2/v2/Vq1) + As + Es = 67.6KB.
// Accumulator columns are tx + 16*j (interleaved) for conflict-free LDS.64.
// grid = (qt=4, p=256, h=8), block = 128.
// ---------------------------------------------------------------------------
__global__ __launch_bounds__(128)
void attn_kernel(const float* __restrict__ proj,
                 const float* __restrict__ k1w,
                 const float* __restrict__ vq1,
                 float* __restrict__ z,
                 float* __restrict__ s_part)
{
    int qt = blockIdx.x;
    int p  = blockIdx.y;
    int h  = blockIdx.z;
    if (qt * 64 + 63 < p) return;

    extern __shared__ unsigned long long sm_dyn[];
    unsigned long long* Bd = sm_dyn;                         // 64*SST ULL (dup B)
    float* As = reinterpret_cast<float*>(sm_dyn + 64 * SST); // q [i][q], then St [j][q]
    float* Es = As + 64 * SST;                               // e [t][q], then A2t [c][q]

    const float* qmat = proj + 2 * D + h * 64;           // [q][i], ld=5D
    const float* k2m  = proj + 1 * D + h * 64;           // [t][j], ld=5D
    const float* v2m  = proj + 4 * D + h * 64;           // [t][c], ld=5D
    const float* Bp   = k1w + ((long long)h * T + p) * (DH * DH);  // [j*64+i]
    const float* Vq   = vq1 + ((long long)h * T + p) * (DH * DH);  // [c*64+e]

    int tid = threadIdx.x;
    int ty = tid >> 4, tx = tid & 15;
    int q0 = qt * 64;

    // ---- Phase 1 fills: As[i][q] = q tile, Bd[i][j] = dup K1W ----
    #pragma unroll 8
    for (int i = tid; i < 4096; i += 128) {
        int r = i >> 6, kk = i & 63;
        As[kk * SST + r] = qmat[(long long)(q0 + r) * (5 * D) + kk];
    }
    #pragma unroll 8
    for (int i = tid; i < 4096; i += 128) {
        int j = i >> 6, ii = i & 63;
        unsigned long long d; DUP2(d, Bp[i]);
        Bd[ii * SST + j] = d;
    }
    __syncthreads();

    // ---- Phase 1: St[q][j] = sum_i q[q,i] * K1W[j,i];  cols j = tx+16*jj ----
    unsigned long long st2[4][4];
    #pragma unroll
    for (int i = 0; i < 4; i++)
        #pragma unroll
        for (int j = 0; j < 4; j++) st2[i][j] = 0ULL;
    GEMM64D(st2, As, Bd);
    __syncthreads();                     // reads of As/Bd done

    // store St transposed into As: As[j][q], j = tx+16*jj
    #pragma unroll
    for (int ip = 0; ip < 4; ip++)
        #pragma unroll
        for (int j = 0; j < 4; j++) {
            As[(tx + 16 * j) * SST + ty * 8 + ip * 2 + 0] = lo2(st2[ip][j]);
            As[(tx + 16 * j) * SST + ty * 8 + ip * 2 + 1] = hi2(st2[ip][j]);
        }

    float srow[8];
    #pragma unroll
    for (int r = 0; r < 8; r++) srow[r] = 0.0f;

    unsigned long long accA[4][4];       // A2 tile acc [qpair][c], c = tx+16j
    #pragma unroll
    for (int i = 0; i < 4; i++)
        #pragma unroll
        for (int j = 0; j < 4; j++) accA[i][j] = 0ULL;

    // ---- Phase 2: t-tiles ----
    for (int tt = 0; tt <= qt; tt++) {
        int t0 = tt * 64;
        __syncthreads();   // prev GEMM2 done with Bd/Es; St store visible (tt=0)

        // fill Bd[j][t] = dup k2
        #pragma unroll 8
        for (int i = tid; i < 4096; i += 128) {
            int t = i >> 6, jj = i & 63;
            unsigned long long d; DUP2(d, k2m[(long long)(t0 + t) * (5 * D) + jj]);
            Bd[jj * SST + t] = d;
        }
        __syncthreads();

        // GEMM1: e[q][t] = St @ k2^T (contract j);  cols t = tx+16j
        unsigned long long e2[4][4];
        #pragma unroll
        for (int i = 0; i < 4; i++)
            #pragma unroll
            for (int j = 0; j < 4; j++) e2[i][j] = 0ULL;
        GEMM64D(e2, As, Bd);
        __syncthreads();                 // Bd(k2) reads done

        // exp + mask -> Es[t][q]  +  fill Bd[t][c] = dup v2
        bool diag = (tt == qt);
        #pragma unroll
        for (int ip = 0; ip < 4; ip++) {
            #pragma unroll
            for (int half = 0; half < 2; half++) {
                int r = ip * 2 + half;
                int q = q0 + ty * 8 + r;
                bool vrow = (q >= p);
                float x0 = half ? hi2(e2[ip][0]) : lo2(e2[ip][0]);
                float x1 = half ? hi2(e2[ip][1]) : lo2(e2[ip][1]);
                float x2 = half ? hi2(e2[ip][2]) : lo2(e2[ip][2]);
                float x3 = half ? hi2(e2[ip][3]) : lo2(e2[ip][3]);
                float e0 = (vrow && (!diag || t0 + tx +  0 <= q)) ? __expf(x0 * 0.015625f) : 0.0f;
                float e1 = (vrow && (!diag || t0 + tx + 16 <= q)) ? __expf(x1 * 0.015625f) : 0.0f;
                float e2v = (vrow && (!diag || t0 + tx + 32 <= q)) ? __expf(x2 * 0.015625f) : 0.0f;
                float e3 = (vrow && (!diag || t0 + tx + 48 <= q)) ? __expf(x3 * 0.015625f) : 0.0f;
                srow[r] += (e0 + e1) + (e2v + e3);
                int qc = ty * 8 + r;
                Es[(tx +  0) * SST + qc] = e0;
                Es[(tx + 16) * SST + qc] = e1;
                Es[(tx + 32) * SST + qc] = e2v;
                Es[(tx + 48) * SST + qc] = e3;
            }
        }
        #pragma unroll 8
        for (int i = tid; i < 4096; i += 128) {
            int t = i >> 6, c = i & 63;
            unsigned long long d; DUP2(d, v2m[(long long)(t0 + t) * (5 * D) + c]);
            Bd[t * SST + c] = d;
        }
        __syncthreads();

        // GEMM2: A2acc[q][c] += Es[t][q] * v2[t][c]  (contract t)
        GEMM64D(accA, Es, Bd);
    }

    __syncthreads();                     // GEMM2 done reading Es/Bd

    // ---- GEMM3 prep: Es[c][q] = A2acc^T (c = tx+16j), Bd[c][e] = dup Vq1 ----
    #pragma unroll
    for (int ip = 0; ip < 4; ip++)
        #pragma unroll
        for (int j = 0; j < 4; j++) {
            Es[(tx + 16 * j) * SST + ty * 8 + ip * 2 + 0] = lo2(accA[ip][j]);
            Es[(tx + 16 * j) * SST + ty * 8 + ip * 2 + 1] = hi2(accA[ip][j]);
        }
    #pragma unroll 8
    for (int i = tid; i < 4096; i += 128) {
        int c = i >> 6, e = i & 63;
        unsigned long long d; DUP2(d, Vq[i]);
        Bd[c * SST + e] = d;
    }
    __syncthreads();

    unsigned long long zacc[4][4];
    #pragma unroll
    for (int i = 0; i < 4; i++)
        #pragma unroll
        for (int j = 0; j < 4; j++) zacc[i][j] = 0ULL;
    GEMM64D(zacc, Es, Bd);

    #pragma unroll
    for (int ip = 0; ip < 4; ip++) {
        #pragma unroll
        for (int half = 0; half < 2; half++) {
            int q = q0 + ty * 8 + ip * 2 + half;
            float* dst = &z[(long long)q * (H * DH) + h * 64 + tx];
            atomicAdd(&dst[0],  half ? hi2(zacc[ip][0]) : lo2(zacc[ip][0]));
            atomicAdd(&dst[16], half ? hi2(zacc[ip][1]) : lo2(zacc[ip][1]));
            atomicAdd(&dst[32], half ? hi2(zacc[ip][2]) : lo2(zacc[ip][2]));
            atomicAdd(&dst[48], half ? hi2(zacc[ip][3]) : lo2(zacc[ip][3]));
        }
    }

    // ---- s_part ----
    #pragma unroll
    for (int r = 0; r < 8; r++) {
        float s = srow[r];
        s += __shfl_xor_sync(0xffffffffu, s, 1);
        s += __shfl_xor_sync(0xffffffffu, s, 2);
        s += __shfl_xor_sync(0xffffffffu, s, 4);
        s += __shfl_xor_sync(0xffffffffu, s, 8);
        if (tx == 0)
            s_part[((long long)(h * T + p)) * T + q0 + ty * 8 + r] = s;
    }
}

// ---------------------------------------------------------------------------
// rowinv[h,q] = 1 / sum_{p<=q} s_part[h][p][q]
// ---------------------------------------------------------------------------
__global__ void rowinv_kernel(const float* __restrict__ s_part,
                              float* __restrict__ rowinv)
{
    int q = blockIdx.x, h = blockIdx.y;
    int tid = threadIdx.x;    // 256, tid == p
    float s = (tid <= q) ? s_part[((long long)(h * T + tid)) * T + q] : 0.0f;
    __shared__ float sh[256];
    sh[tid] = s;
    __syncthreads();
    for (int o = 128; o > 0; o >>= 1) {
        if (tid < o) sh[tid] += sh[tid + o];
        __syncthreads();
    }
    if (tid == 0) rowinv[h * T + q] = 1.0f / sh[0];
}

// ---------------------------------------------------------------------------
static inline void launch_gemm(const float* A, long long aH, long long aP, int lda,
                               const float* B, long long bH, long long bP, int ldb,
                               float* C, long long cH, long long cP, int ldc,
                               int M, int N, int K, int P, int batch,
                               int transB, const float* bias,
                               const float* rowscale, int rsH,
                               int mode, int ksplit)
{
    dim3 grid(N / 64, M / 64, batch * ksplit);
    gemm_kernel<<<grid, 128>>>(A, B, C, lda, ldb, ldc, M, N, K, P,
                               aH, aP, bH, bP, cH, cP,
                               transB, bias, rowscale, rsH, mode, ksplit);
}

extern "C" void kernel_launch(void* const* d_in, const int* in_sizes, int n_in,
                              void* d_out, int out_size)
{
    const float* x    = (const float*)d_in[0];
    const float* Wk   = (const float*)d_in[1];
    const float* bk   = (const float*)d_in[2];
    const float* WKq  = (const float*)d_in[3];
    const float* WVq  = (const float*)d_in[4];
    const float* Wout = (const float*)d_in[5];
    const float* bout = (const float*)d_in[6];
    float* out = (float*)d_out;

    float *proj, *k1w, *vq1, *spart, *rinv, *z;
    cudaGetSymbolAddress((void**)&proj,  g_proj);
    cudaGetSymbolAddress((void**)&k1w,   g_K1W);
    cudaGetSymbolAddress((void**)&vq1,   g_Vq1);
    cudaGetSymbolAddress((void**)&spart, g_spart);
    cudaGetSymbolAddress((void**)&rinv,  g_rowinv);
    cudaGetSymbolAddress((void**)&z,     g_z);

    const long long HPJ = (long long)T * DH * DH;

    // 1) proj = x @ W_kkqvv + b
    launch_gemm(x, 0, 0, D, Wk, 0, 0, 5 * D, proj, 0, 0, 5 * D,
                T, 5 * D, D, 1, 1, 0, bk, nullptr, 0, 0, 1);

    // 2) K1W[h] = k1_h @ W_Kq[h]
    launch_gemm(proj + 0, 64, 0, 5 * D, WKq, (long long)DH * DH * DH, 0, DH * DH,
                k1w, HPJ, 0, DH * DH,
                T, DH * DH, DH, 1, H, 0, nullptr, nullptr, 0, 0, 1);

    // 3) Vq1[h] = v1_h @ W_Vq[h]
    launch_gemm(proj + 3 * D, 64, 0, 5 * D, WVq, (long long)DH * DH * DH, 0, DH * DH,
                vq1, HPJ, 0, DH * DH,
                T, DH * DH, DH, 1, H, 0, nullptr, nullptr, 0, 0, 1);

    // 4) zero z, then fused attention inner (z via atomics) + partial sums
    cudaMemsetAsync(z, 0, (size_t)T * H * DH * sizeof(float));
    {
        int smem_bytes = 64 * SST * 8 + 2 * 64 * SST * 4;   // Bd + As + Es = 67584
        cudaFuncSetAttribute(attn_kernel,
                             cudaFuncAttributeMaxDynamicSharedMemorySize, smem_bytes);
        dim3 grid(T / 64, T, H);
        attn_kernel<<<grid, 128, smem_bytes>>>(proj, k1w, vq1, z, spart);
    }

    // 5) rowinv
    {
        dim3 grid(T, H);
        rowinv_kernel<<<grid, 256>>>(spart, rinv);
    }

    // 6) out = (z * rinv-per-(h,q)) @ W_out + b_out   (mode 5 scales A-loads)
    launch_gemm(z, 0, 0, H * DH, Wout, 0, 0, D,
                out, 0, 0, D,
                T, D, H * DH, 1, 1, 0, bout, rinv, 0, 5, 1);
}